// round 1
// baseline (speedup 1.0000x reference)
#include <cuda_runtime.h>
#include <cuda_bf16.h>
#include <stdint.h>

#define EMB 64

// One edge handled by 16 consecutive threads (half-warp). Each thread owns one
// float4 (4 of the 64 embedding dims). Gather of src row is a coalesced 256B
// read; scatter is a 128-bit vector atomic (RED.E.ADD.F32 .128) to L2.
__global__ void spmm_scatter(const int* __restrict__ row,
                             const int* __restrict__ col,
                             const float* __restrict__ val,
                             const float* __restrict__ src,
                             float* __restrict__ dst,
                             int E) {
    long long t = (long long)blockIdx.x * blockDim.x + threadIdx.x;
    int edge = (int)(t >> 4);
    int lane = (int)(t & 15);
    if (edge >= E) return;

    int r = __ldg(row + edge);
    int c = __ldg(col + edge);
    float v = __ldg(val + edge);

    const float4* s = reinterpret_cast<const float4*>(src + (size_t)c * EMB);
    float4 x = __ldg(s + lane);
    float4 y = make_float4(x.x * v, x.y * v, x.z * v, x.w * v);

    float4* d = reinterpret_cast<float4*>(dst + (size_t)r * EMB) + lane;
#if __CUDA_ARCH__ >= 900
    atomicAdd(d, y);
#else
    atomicAdd(&d->x, y.x); atomicAdd(&d->y, y.y);
    atomicAdd(&d->z, y.z); atomicAdd(&d->w, y.w);
#endif
}

// out[i] = mean of the 4 stacked layers, vectorized float4, grid-stride.
__global__ void mean4_kernel(const float4* __restrict__ s0,
                             const float4* __restrict__ s1,
                             const float4* __restrict__ s2,
                             const float4* __restrict__ s3,
                             float4* __restrict__ out,
                             size_t n4) {
    size_t i = (size_t)blockIdx.x * blockDim.x + threadIdx.x;
    size_t stride = (size_t)gridDim.x * blockDim.x;
    for (; i < n4; i += stride) {
        float4 a = s0[i], b = s1[i], c = s2[i], d = s3[i];
        float4 o;
        o.x = 0.25f * (a.x + b.x + c.x + d.x);
        o.y = 0.25f * (a.y + b.y + c.y + d.y);
        o.z = 0.25f * (a.z + b.z + c.z + d.z);
        o.w = 0.25f * (a.w + b.w + c.w + d.w);
        out[i] = o;
    }
}

extern "C" void kernel_launch(void* const* d_in, const int* in_sizes, int n_in,
                              void* d_out, int out_size) {
    const float* user_emb = (const float*)d_in[0];
    const float* item_emb = (const float*)d_in[1];
    const int*   edge_row = (const int*)d_in[2];
    const int*   edge_col = (const int*)d_in[3];
    const float* edge_val = (const float*)d_in[4];

    const int U = in_sizes[0] / EMB;          // 200000
    const int I = in_sizes[1] / EMB;          // 100000
    const int E = in_sizes[2];                // 4000000
    const size_t N = (size_t)U + I;           // 300000
    const size_t F = N * EMB;                 // 19.2M floats per layer

    float* out     = (float*)d_out;
    float* final_e = out;                     // [0, F)   = final_user ‖ final_item
    float* stacked = out + F;                 // [F, 5F)  = 4 layer snapshots

    // ---- layer 0: concat(user_emb, item_emb) ----
    cudaMemcpyAsync(stacked,                 user_emb, (size_t)in_sizes[0] * sizeof(float),
                    cudaMemcpyDeviceToDevice);
    cudaMemcpyAsync(stacked + (size_t)U * EMB, item_emb, (size_t)in_sizes[1] * sizeof(float),
                    cudaMemcpyDeviceToDevice);

    // ---- 3 propagation layers ----
    const int threads = 256;
    const long long total_t = (long long)E * 16;
    const int blocks = (int)((total_t + threads - 1) / threads);

    for (int l = 1; l <= 3; l++) {
        const float* src = stacked + (size_t)(l - 1) * F;
        float*       dst = stacked + (size_t)l * F;
        cudaMemsetAsync(dst, 0, F * sizeof(float));
        spmm_scatter<<<blocks, threads>>>(edge_row, edge_col, edge_val, src, dst, E);
    }

    // ---- final = mean over the 4 layers ----
    const size_t n4 = F / 4;
    int mblocks = 1480;  // ~10 blocks/SM grid-stride
    mean4_kernel<<<mblocks, 256>>>(
        (const float4*)(stacked),
        (const float4*)(stacked + F),
        (const float4*)(stacked + 2 * F),
        (const float4*)(stacked + 3 * F),
        (float4*)final_e, n4);
}

// round 4
// speedup vs baseline: 1.9993x; 1.9993x over previous
#include <cuda_runtime.h>
#include <cuda_bf16.h>
#include <stdint.h>

#define EMB 64
#define MAXN 300001
#define MAXE 4200000
#define TILE 4096   // scan tile: 256 threads x 16 elems

// ---- scratch (static device globals; no runtime allocation) ----
__device__ int  g_rowptr[MAXN + 1];
__device__ int  g_cursor[MAXN];      // doubles as degree histogram
__device__ int  g_tilesum[512];
__device__ int2 g_colval[MAXE];      // (col, bitcast(val)) in CSR order

// ---------------- CSR build ----------------
__global__ void zero_cursor(int n) {
    int i = blockIdx.x * blockDim.x + threadIdx.x;
    if (i < n) g_cursor[i] = 0;
}

__global__ void hist_kernel(const int* __restrict__ row, int E) {
    int e = blockIdx.x * blockDim.x + threadIdx.x;
    if (e < E) atomicAdd(&g_cursor[row[e]], 1);
}

// per-tile exclusive scan of degrees (g_cursor) -> g_rowptr, tile totals -> g_tilesum
__global__ void scanA(int n) {
    __shared__ int ssum[256];
    int base = blockIdx.x * TILE + threadIdx.x * 16;
    int v[16]; int run = 0;
#pragma unroll
    for (int k = 0; k < 16; k++) {
        int i = base + k;
        int d = (i < n) ? g_cursor[i] : 0;
        v[k] = run; run += d;
    }
    ssum[threadIdx.x] = run;
    __syncthreads();
    for (int off = 1; off < 256; off <<= 1) {
        int t = (threadIdx.x >= off) ? ssum[threadIdx.x - off] : 0;
        __syncthreads();
        ssum[threadIdx.x] += t;
        __syncthreads();
    }
    int texcl = (threadIdx.x == 0) ? 0 : ssum[threadIdx.x - 1];
#pragma unroll
    for (int k = 0; k < 16; k++) {
        int i = base + k;
        if (i < n) g_rowptr[i] = texcl + v[k];
    }
    if (threadIdx.x == 255) g_tilesum[blockIdx.x] = ssum[255];
}

__global__ void scanB(int ntiles) {
    if (threadIdx.x == 0 && blockIdx.x == 0) {
        int run = 0;
        for (int t = 0; t < ntiles; t++) {
            int tmp = g_tilesum[t];
            g_tilesum[t] = run;
            run += tmp;
        }
    }
}

__global__ void scanC(int n, int E) {
    int i = blockIdx.x * blockDim.x + threadIdx.x;
    if (i < n) {
        int val = g_rowptr[i] + g_tilesum[i >> 12];   // TILE == 2^12
        g_rowptr[i] = val;
        g_cursor[i] = val;          // fill cursor starts at row start
        if (i == 0) g_rowptr[n] = E;
    }
}

__global__ void build_kernel(const int* __restrict__ row,
                             const int* __restrict__ col,
                             const float* __restrict__ val, int E) {
    int e = blockIdx.x * blockDim.x + threadIdx.x;
    if (e < E) {
        int r = row[e];
        int pos = atomicAdd(&g_cursor[r], 1);
        g_colval[pos] = make_int2(col[e], __float_as_int(val[e]));
    }
}

// ---------------- pull-mode SpMM: half-warp (16 lanes) per dst row ----------------
__device__ __forceinline__ float4 gather_row(const float* __restrict__ src,
                                             int r, int lane, unsigned mask) {
    int s  = __ldg(&g_rowptr[r]);
    int e2 = __ldg(&g_rowptr[r + 1]);
    float4 acc = make_float4(0.f, 0.f, 0.f, 0.f);
    for (int base = s; base < e2; base += 16) {
        int idx = base + lane;
        int2 cv = (idx < e2) ? g_colval[idx] : make_int2(0, 0);
        int cnt = e2 - base; if (cnt > 16) cnt = 16;
#pragma unroll 4
        for (int j = 0; j < 16; j++) {
            if (j >= cnt) break;
            int   c = __shfl_sync(mask, cv.x, j, 16);
            float v = __int_as_float(__shfl_sync(mask, cv.y, j, 16));
            float4 x = __ldg(reinterpret_cast<const float4*>(src + (size_t)c * EMB) + lane);
            acc.x += v * x.x; acc.y += v * x.y;
            acc.z += v * x.z; acc.w += v * x.w;
        }
    }
    return acc;
}

__global__ void __launch_bounds__(256)
spmm_layer(const float* __restrict__ src, float* __restrict__ dst, int n) {
    int t = blockIdx.x * blockDim.x + threadIdx.x;
    int r = t >> 4, lane = t & 15;
    if (r >= n) return;
    unsigned mask = 0xFFFFu << (threadIdx.x & 16);
    float4 acc = gather_row(src, r, lane, mask);
    reinterpret_cast<float4*>(dst + (size_t)r * EMB)[lane] = acc;
}

// last layer: write stacked[3] AND final mean of the 4 layers
__global__ void __launch_bounds__(256)
spmm_layer_final(const float* __restrict__ s0,
                 const float* __restrict__ s1,
                 const float* __restrict__ s2,
                 float* __restrict__ s3,
                 float* __restrict__ fin, int n) {
    int t = blockIdx.x * blockDim.x + threadIdx.x;
    int r = t >> 4, lane = t & 15;
    if (r >= n) return;
    unsigned mask = 0xFFFFu << (threadIdx.x & 16);
    float4 acc = gather_row(s2, r, lane, mask);       // layer3 = A @ layer2
    size_t off = (size_t)r * EMB;
    reinterpret_cast<float4*>(s3 + off)[lane] = acc;
    float4 a = __ldg(reinterpret_cast<const float4*>(s0 + off) + lane);
    float4 b = __ldg(reinterpret_cast<const float4*>(s1 + off) + lane);
    float4 c = __ldg(reinterpret_cast<const float4*>(s2 + off) + lane);
    float4 o;
    o.x = 0.25f * (a.x + b.x + c.x + acc.x);
    o.y = 0.25f * (a.y + b.y + c.y + acc.y);
    o.z = 0.25f * (a.z + b.z + c.z + acc.z);
    o.w = 0.25f * (a.w + b.w + c.w + acc.w);
    reinterpret_cast<float4*>(fin + off)[lane] = o;
}

extern "C" void kernel_launch(void* const* d_in, const int* in_sizes, int n_in,
                              void* d_out, int out_size) {
    const float* user_emb = (const float*)d_in[0];
    const float* item_emb = (const float*)d_in[1];
    const int*   edge_row = (const int*)d_in[2];
    const int*   edge_col = (const int*)d_in[3];
    const float* edge_val = (const float*)d_in[4];

    const int U = in_sizes[0] / EMB;
    const int I = in_sizes[1] / EMB;
    const int E = in_sizes[2];
    const int N = U + I;
    const size_t F = (size_t)N * EMB;

    float* out     = (float*)d_out;
    float* final_e = out;            // final_user ‖ final_item
    float* stacked = out + F;        // 4 layer snapshots

    // layer 0 = concat(user_emb, item_emb)
    cudaMemcpyAsync(stacked, user_emb, (size_t)in_sizes[0] * sizeof(float),
                    cudaMemcpyDeviceToDevice);
    cudaMemcpyAsync(stacked + (size_t)U * EMB, item_emb,
                    (size_t)in_sizes[1] * sizeof(float), cudaMemcpyDeviceToDevice);

    // ---- CSR build ----
    const int T = 256;
    zero_cursor<<<(N + T - 1) / T, T>>>(N);
    hist_kernel<<<(E + T - 1) / T, T>>>(edge_row, E);
    int ntiles = (N + TILE - 1) / TILE;
    scanA<<<ntiles, 256>>>(N);
    scanB<<<1, 32>>>(ntiles);
    scanC<<<(N + T - 1) / T, T>>>(N, E);
    build_kernel<<<(E + T - 1) / T, T>>>(edge_row, edge_col, edge_val, E);

    // ---- 3 propagation layers (pull-mode, no atomics) ----
    int gblocks = (N * 16 + T - 1) / T;
    spmm_layer<<<gblocks, T>>>(stacked,     stacked + F,     N);
    spmm_layer<<<gblocks, T>>>(stacked + F, stacked + 2 * F, N);
    spmm_layer_final<<<gblocks, T>>>(stacked, stacked + F, stacked + 2 * F,
                                     stacked + 3 * F, final_e, N);
}